// round 1
// baseline (speedup 1.0000x reference)
#include <cuda_runtime.h>
#include <cuda_bf16.h>
#include <cstdint>

#define N_ROWS      12288        // L1_INPUT_SIZE
#define N_COLS      1030         // L1_OUTPUT_SIZE
#define HID         1024
#define STRIDE      1040         // padded bf16 row stride (2080 B, 16B aligned)
#define BATCH       8192
#define NFEAT       32
#define L2IN        2048
#define PSQT_K      0.08f        // 0.5 / (400/64)

// bf16 copy of W1, padded row stride (module-static, no runtime alloc)
__device__ __nv_bfloat16 g_W1bf[(size_t)N_ROWS * STRIDE];

// ---------------------------------------------------------------------------
// W1 fp32 -> bf16 conversion (runs every launch; deterministic)
// ---------------------------------------------------------------------------
__global__ void convert_kernel(const float* __restrict__ W1) {
    int c = blockIdx.x * blockDim.x + threadIdx.x;
    int r = blockIdx.y;
    if (c < N_COLS) {
        g_W1bf[(size_t)r * STRIDE + c] = __float2bfloat16(W1[(size_t)r * N_COLS + c]);
    }
}

// ---------------------------------------------------------------------------
// Unpack helpers: u32 holding two bf16 (lo = lower column)
// ---------------------------------------------------------------------------
__device__ __forceinline__ float bflo(unsigned u) { return __uint_as_float(u << 16); }
__device__ __forceinline__ float bfhi(unsigned u) { return __uint_as_float(u & 0xffff0000u); }

// ---------------------------------------------------------------------------
// Main fused kernel: one CTA per batch row, 128 threads, 8 cols/thread/side
// ---------------------------------------------------------------------------
__global__ __launch_bounds__(128, 8)
void fwd_kernel(const int*   __restrict__ x,
                const int*   __restrict__ y,
                const float* __restrict__ v,
                const int*   __restrict__ s,
                const float* __restrict__ b1,
                const float* __restrict__ W2,
                const float* __restrict__ b2,
                float*       __restrict__ out)
{
    __shared__ int   sx[NFEAT];
    __shared__ int   sy[NFEAT];
    __shared__ float sv[NFEAT];
    __shared__ int   ss_sh;
    __shared__ float red[4];

    const int b = blockIdx.x;
    const int t = threadIdx.x;

    if (t < NFEAT) {
        sx[t] = x[b * NFEAT + t];
        sy[t] = y[b * NFEAT + t];
        sv[t] = v[b * NFEAT + t];
    }
    if (t == 0) ss_sh = s[b];
    __syncthreads();
    const int ss = ss_sh;

    float ax[8] = {0.f, 0.f, 0.f, 0.f, 0.f, 0.f, 0.f, 0.f};
    float ay[8] = {0.f, 0.f, 0.f, 0.f, 0.f, 0.f, 0.f, 0.f};

    // thread t owns bf16 columns [8t, 8t+8) of each side's hidden vector
#pragma unroll 4
    for (int a = 0; a < NFEAT; ++a) {
        const float val = sv[a];
        const uint4* rx = reinterpret_cast<const uint4*>(g_W1bf + (size_t)sx[a] * STRIDE) + t;
        const uint4* ry = reinterpret_cast<const uint4*>(g_W1bf + (size_t)sy[a] * STRIDE) + t;
        const uint4 wx = *rx;
        const uint4 wy = *ry;

        ax[0] = fmaf(val, bflo(wx.x), ax[0]);
        ax[1] = fmaf(val, bfhi(wx.x), ax[1]);
        ax[2] = fmaf(val, bflo(wx.y), ax[2]);
        ax[3] = fmaf(val, bfhi(wx.y), ax[3]);
        ax[4] = fmaf(val, bflo(wx.z), ax[4]);
        ax[5] = fmaf(val, bfhi(wx.z), ax[5]);
        ax[6] = fmaf(val, bflo(wx.w), ax[6]);
        ax[7] = fmaf(val, bfhi(wx.w), ax[7]);

        ay[0] = fmaf(val, bflo(wy.x), ay[0]);
        ay[1] = fmaf(val, bfhi(wy.x), ay[1]);
        ay[2] = fmaf(val, bflo(wy.y), ay[2]);
        ay[3] = fmaf(val, bfhi(wy.y), ay[3]);
        ay[4] = fmaf(val, bflo(wy.z), ay[4]);
        ay[5] = fmaf(val, bfhi(wy.z), ay[5]);
        ay[6] = fmaf(val, bflo(wy.w), ay[6]);
        ay[7] = fmaf(val, bfhi(wy.w), ay[7]);
    }

    // ---- epilogue: relu(acc + b1) dot W2[ss] for both halves ----
    const int col0 = t * 8;
    const float4 b1a = *reinterpret_cast<const float4*>(b1 + col0);
    const float4 b1b = *reinterpret_cast<const float4*>(b1 + col0 + 4);
    const float* w2row = W2 + (size_t)ss * L2IN;
    const float4 wxa = *reinterpret_cast<const float4*>(w2row + col0);
    const float4 wxb = *reinterpret_cast<const float4*>(w2row + col0 + 4);
    const float4 wya = *reinterpret_cast<const float4*>(w2row + HID + col0);
    const float4 wyb = *reinterpret_cast<const float4*>(w2row + HID + col0 + 4);

    float local = 0.f;
    local = fmaf(fmaxf(ax[0] + b1a.x, 0.f), wxa.x, local);
    local = fmaf(fmaxf(ax[1] + b1a.y, 0.f), wxa.y, local);
    local = fmaf(fmaxf(ax[2] + b1a.z, 0.f), wxa.z, local);
    local = fmaf(fmaxf(ax[3] + b1a.w, 0.f), wxa.w, local);
    local = fmaf(fmaxf(ax[4] + b1b.x, 0.f), wxb.x, local);
    local = fmaf(fmaxf(ax[5] + b1b.y, 0.f), wxb.y, local);
    local = fmaf(fmaxf(ax[6] + b1b.z, 0.f), wxb.z, local);
    local = fmaf(fmaxf(ax[7] + b1b.w, 0.f), wxb.w, local);

    local = fmaf(fmaxf(ay[0] + b1a.x, 0.f), wya.x, local);
    local = fmaf(fmaxf(ay[1] + b1a.y, 0.f), wya.y, local);
    local = fmaf(fmaxf(ay[2] + b1a.z, 0.f), wya.z, local);
    local = fmaf(fmaxf(ay[3] + b1a.w, 0.f), wya.w, local);
    local = fmaf(fmaxf(ay[4] + b1b.x, 0.f), wyb.x, local);
    local = fmaf(fmaxf(ay[5] + b1b.y, 0.f), wyb.y, local);
    local = fmaf(fmaxf(ay[6] + b1b.z, 0.f), wyb.z, local);
    local = fmaf(fmaxf(ay[7] + b1b.w, 0.f), wyb.w, local);

    // ---- psqt term: (x2 - y2) * PSQT_K ; b1 cancels in the difference ----
    // threads 0..31 -> x side feature t ; threads 32..63 -> y side feature t-32
    if (t < 64) {
        const int a   = t & 31;
        const int idx = (t < 32) ? sx[a] : sy[a];
        const float w = __bfloat162float(g_W1bf[(size_t)idx * STRIDE + HID + ss]);
        const float p = sv[a] * w * PSQT_K;
        local += (t < 32) ? p : -p;
    }

    // ---- block reduction ----
#pragma unroll
    for (int o = 16; o > 0; o >>= 1)
        local += __shfl_down_sync(0xffffffffu, local, o);
    if ((t & 31) == 0) red[t >> 5] = local;
    __syncthreads();
    if (t == 0) {
        float c = red[0] + red[1] + red[2] + red[3] + b2[ss];
        out[b] = 1.0f / (1.0f + expf(-c));
    }
}

// ---------------------------------------------------------------------------
extern "C" void kernel_launch(void* const* d_in, const int* in_sizes, int n_in,
                              void* d_out, int out_size)
{
    const int*   x  = (const int*)  d_in[0];
    const int*   y  = (const int*)  d_in[1];
    const float* v  = (const float*)d_in[2];
    const int*   s  = (const int*)  d_in[3];
    const float* W1 = (const float*)d_in[4];
    const float* b1 = (const float*)d_in[5];
    const float* W2 = (const float*)d_in[6];
    const float* b2 = (const float*)d_in[7];
    float* out = (float*)d_out;

    dim3 cgrid((N_COLS + 255) / 256, N_ROWS);
    convert_kernel<<<cgrid, 256>>>(W1);
    fwd_kernel<<<BATCH, 128>>>(x, y, v, s, b1, W2, b2, out);
}

// round 2
// speedup vs baseline: 1.9096x; 1.9096x over previous
#include <cuda_runtime.h>
#include <cuda_bf16.h>
#include <cuda_fp16.h>
#include <cuda_fp8.h>
#include <cstdint>

#define N_ROWS      12288        // L1_INPUT_SIZE
#define N_COLS      1030         // L1_OUTPUT_SIZE
#define HID         1024
#define STRIDE8     1032         // padded fp8 row stride bytes (8B aligned)
#define BATCH       8192
#define NFEAT       32
#define L2IN        2048
#define W_SCALE     128.0f       // weight scale into e4m3 normal range
#define INV_SCALE   0.0078125f   // 1/128
#define PSQT_K      0.08f        // 0.5 / (400/64)

// fp8(e4m3) copy of W1*128, padded row stride (module-static, no runtime alloc)
__device__ unsigned char g_W1f8[(size_t)N_ROWS * STRIDE8];

// ---------------------------------------------------------------------------
// W1 fp32 -> fp8 conversion (runs every launch; deterministic)
// one thread per 4 padded columns; float2 reads, u32 (fp8x4) write
// ---------------------------------------------------------------------------
#define GPR 258                  // groups of 4 per padded row (1032/4)
__global__ void convert_kernel(const float* __restrict__ W1) {
    int gid = blockIdx.x * blockDim.x + threadIdx.x;
    if (gid >= N_ROWS * GPR) return;
    const int r   = gid / GPR;
    const int g   = gid - r * GPR;
    const int col = g * 4;
    const float* src = W1 + (size_t)r * N_COLS + col;

    float4 w;
    if (col + 4 <= N_COLS) {
        const float2 a = *reinterpret_cast<const float2*>(src);
        const float2 b = *reinterpret_cast<const float2*>(src + 2);
        w = make_float4(a.x, a.y, b.x, b.y);
    } else {
        w.x = (col + 0 < N_COLS) ? src[0] : 0.f;
        w.y = (col + 1 < N_COLS) ? src[1] : 0.f;
        w.z = (col + 2 < N_COLS) ? src[2] : 0.f;
        w.w = (col + 3 < N_COLS) ? src[3] : 0.f;
    }
    const __nv_fp8x2_storage_t lo =
        __nv_cvt_float2_to_fp8x2(make_float2(w.x * W_SCALE, w.y * W_SCALE),
                                 __NV_SATFINITE, __NV_E4M3);
    const __nv_fp8x2_storage_t hi =
        __nv_cvt_float2_to_fp8x2(make_float2(w.z * W_SCALE, w.w * W_SCALE),
                                 __NV_SATFINITE, __NV_E4M3);
    const uint32_t packed = (uint32_t)lo | ((uint32_t)hi << 16);
    *reinterpret_cast<uint32_t*>(g_W1f8 + (size_t)r * STRIDE8 + col) = packed;
}

// ---------------------------------------------------------------------------
// unpack u32 (4×e4m3) -> two half2, fused multiply-accumulate with vh
// ---------------------------------------------------------------------------
__device__ __forceinline__ void fma4_fp8(half2& a0, half2& a1, uint32_t w, half2 vh) {
    uint32_t h0, h1;
    asm("{\n\t"
        ".reg .b16 lo, hi;\n\t"
        "mov.b32 {lo, hi}, %2;\n\t"
        "cvt.rn.f16x2.e4m3x2 %0, lo;\n\t"
        "cvt.rn.f16x2.e4m3x2 %1, hi;\n\t"
        "}" : "=r"(h0), "=r"(h1) : "r"(w));
    a0 = __hfma2(*reinterpret_cast<half2*>(&h0), vh, a0);
    a1 = __hfma2(*reinterpret_cast<half2*>(&h1), vh, a1);
}

// ---------------------------------------------------------------------------
// Main fused kernel: one CTA per batch row, 128 threads, 8 cols/thread/side
// ---------------------------------------------------------------------------
__global__ __launch_bounds__(128)
void fwd_kernel(const int*   __restrict__ x,
                const int*   __restrict__ y,
                const float* __restrict__ v,
                const int*   __restrict__ s,
                const float* __restrict__ b1,
                const float* __restrict__ W2,
                const float* __restrict__ b2,
                float*       __restrict__ out)
{
    __shared__ int   sx[NFEAT];
    __shared__ int   sy[NFEAT];
    __shared__ float sv[NFEAT];
    __shared__ half2 svh[NFEAT];
    __shared__ int   ss_sh;
    __shared__ float red[4];

    const int b = blockIdx.x;
    const int t = threadIdx.x;

    if (t < NFEAT) {
        sx[t] = x[b * NFEAT + t];
        sy[t] = y[b * NFEAT + t];
        const float vv = v[b * NFEAT + t];
        sv[t]  = vv;
        svh[t] = __float2half2_rn(vv);
    }
    if (t == 0) ss_sh = s[b];
    __syncthreads();
    const int ss = ss_sh;

    half2 ax[4], ay[4];
#pragma unroll
    for (int j = 0; j < 4; ++j) { ax[j] = __float2half2_rn(0.f); ay[j] = __float2half2_rn(0.f); }

    const size_t toff = (size_t)t * 8;

    // thread t owns fp8 columns [8t, 8t+8) of each side's hidden vector
#pragma unroll 4
    for (int a = 0; a < NFEAT; ++a) {
        const half2 vh = svh[a];
        const uint2 wx = *reinterpret_cast<const uint2*>(g_W1f8 + (size_t)sx[a] * STRIDE8 + toff);
        const uint2 wy = *reinterpret_cast<const uint2*>(g_W1f8 + (size_t)sy[a] * STRIDE8 + toff);
        fma4_fp8(ax[0], ax[1], wx.x, vh);
        fma4_fp8(ax[2], ax[3], wx.y, vh);
        fma4_fp8(ay[0], ay[1], wy.x, vh);
        fma4_fp8(ay[2], ay[3], wy.y, vh);
    }

    // ---- epilogue: relu(acc/128 + b1) dot W2[ss] for both halves ----
    const int col0 = t * 8;
    const float4 b1a = *reinterpret_cast<const float4*>(b1 + col0);
    const float4 b1b = *reinterpret_cast<const float4*>(b1 + col0 + 4);
    const float* w2row = W2 + (size_t)ss * L2IN;
    const float4 wxa = *reinterpret_cast<const float4*>(w2row + col0);
    const float4 wxb = *reinterpret_cast<const float4*>(w2row + col0 + 4);
    const float4 wya = *reinterpret_cast<const float4*>(w2row + HID + col0);
    const float4 wyb = *reinterpret_cast<const float4*>(w2row + HID + col0 + 4);

    const float2 fx0 = __half22float2(ax[0]);
    const float2 fx1 = __half22float2(ax[1]);
    const float2 fx2 = __half22float2(ax[2]);
    const float2 fx3 = __half22float2(ax[3]);
    const float2 fy0 = __half22float2(ay[0]);
    const float2 fy1 = __half22float2(ay[1]);
    const float2 fy2 = __half22float2(ay[2]);
    const float2 fy3 = __half22float2(ay[3]);

    float local = 0.f;
    local = fmaf(fmaxf(fmaf(fx0.x, INV_SCALE, b1a.x), 0.f), wxa.x, local);
    local = fmaf(fmaxf(fmaf(fx0.y, INV_SCALE, b1a.y), 0.f), wxa.y, local);
    local = fmaf(fmaxf(fmaf(fx1.x, INV_SCALE, b1a.z), 0.f), wxa.z, local);
    local = fmaf(fmaxf(fmaf(fx1.y, INV_SCALE, b1a.w), 0.f), wxa.w, local);
    local = fmaf(fmaxf(fmaf(fx2.x, INV_SCALE, b1b.x), 0.f), wxb.x, local);
    local = fmaf(fmaxf(fmaf(fx2.y, INV_SCALE, b1b.y), 0.f), wxb.y, local);
    local = fmaf(fmaxf(fmaf(fx3.x, INV_SCALE, b1b.z), 0.f), wxb.z, local);
    local = fmaf(fmaxf(fmaf(fx3.y, INV_SCALE, b1b.w), 0.f), wxb.w, local);

    local = fmaf(fmaxf(fmaf(fy0.x, INV_SCALE, b1a.x), 0.f), wya.x, local);
    local = fmaf(fmaxf(fmaf(fy0.y, INV_SCALE, b1a.y), 0.f), wya.y, local);
    local = fmaf(fmaxf(fmaf(fy1.x, INV_SCALE, b1a.z), 0.f), wya.z, local);
    local = fmaf(fmaxf(fmaf(fy1.y, INV_SCALE, b1a.w), 0.f), wya.w, local);
    local = fmaf(fmaxf(fmaf(fy2.x, INV_SCALE, b1b.x), 0.f), wyb.x, local);
    local = fmaf(fmaxf(fmaf(fy2.y, INV_SCALE, b1b.y), 0.f), wyb.y, local);
    local = fmaf(fmaxf(fmaf(fy3.x, INV_SCALE, b1b.z), 0.f), wyb.z, local);
    local = fmaf(fmaxf(fmaf(fy3.y, INV_SCALE, b1b.w), 0.f), wyb.w, local);

    // ---- psqt term: (x2 - y2) * PSQT_K ; b1 cancels in the difference ----
    // threads 0..31 -> x side feature t ; threads 32..63 -> y side feature t-32
    if (t < 64) {
        const int a   = t & 31;
        const int idx = (t < 32) ? sx[a] : sy[a];
        const unsigned char wb = g_W1f8[(size_t)idx * STRIDE8 + HID + ss];
        const float w = __half2float(
            __nv_cvt_fp8_to_halfraw((__nv_fp8_storage_t)wb, __NV_E4M3));
        const float p = sv[a] * w * (PSQT_K * INV_SCALE);
        local += (t < 32) ? p : -p;
    }

    // ---- block reduction ----
#pragma unroll
    for (int o = 16; o > 0; o >>= 1)
        local += __shfl_down_sync(0xffffffffu, local, o);
    if ((t & 31) == 0) red[t >> 5] = local;
    __syncthreads();
    if (t == 0) {
        float c = red[0] + red[1] + red[2] + red[3] + b2[ss];
        out[b] = 1.0f / (1.0f + expf(-c));
    }
}

// ---------------------------------------------------------------------------
extern "C" void kernel_launch(void* const* d_in, const int* in_sizes, int n_in,
                              void* d_out, int out_size)
{
    const int*   x  = (const int*)  d_in[0];
    const int*   y  = (const int*)  d_in[1];
    const float* v  = (const float*)d_in[2];
    const int*   s  = (const int*)  d_in[3];
    const float* W1 = (const float*)d_in[4];
    const float* b1 = (const float*)d_in[5];
    const float* W2 = (const float*)d_in[6];
    const float* b2 = (const float*)d_in[7];
    float* out = (float*)d_out;

    const int total = N_ROWS * GPR;
    convert_kernel<<<(total + 255) / 256, 256>>>(W1);
    fwd_kernel<<<BATCH, 128>>>(x, y, v, s, b1, W2, b2, out);
}